// round 16
// baseline (speedup 1.0000x reference)
#include <cuda_runtime.h>
#include <cuda_fp16.h>
#include <cstdint>
#include <cstddef>

// B=4, N=8192, DIN=512, DINNER=512, DOUT=512, W=128 -> 64 windows/batch, pad=0
#define MTOT 32768

// Scratch (alloc-guard-safe __device__ globals), all fp16
__device__ __half g_x[(size_t)MTOT * 512];
__device__ __half g_wqk[(size_t)1024 * 512];
__device__ __half g_wout[(size_t)512 * 512];
__device__ __half g_qk[(size_t)MTOT * 1024];   // [m][0:512]=Q, [m][512:1024]=K
__device__ __half g_att[(size_t)MTOT * 512];

__device__ __forceinline__ uint32_t h2(float a, float b) {
    __half2 h = __floats2half2_rn(a, b);
    return *(uint32_t*)&h;
}
__device__ __forceinline__ uint32_t smem_u32(const void* p) {
    uint32_t a;
    asm("{ .reg .u64 t; cvta.to.shared.u64 t, %1; cvt.u32.u64 %0, t; }" : "=r"(a) : "l"(p));
    return a;
}
__device__ __forceinline__ void mma16(float* c, uint32_t a0, uint32_t a1, uint32_t a2, uint32_t a3,
                                      uint32_t b0, uint32_t b1) {
    asm volatile("mma.sync.aligned.m16n8k16.row.col.f32.f16.f16.f32 "
                 "{%0,%1,%2,%3}, {%4,%5,%6,%7}, {%8,%9}, {%0,%1,%2,%3};"
                 : "+f"(c[0]), "+f"(c[1]), "+f"(c[2]), "+f"(c[3])
                 : "r"(a0), "r"(a1), "r"(a2), "r"(a3), "r"(b0), "r"(b1));
}
__device__ __forceinline__ void ldsm4(uint32_t* r, uint32_t addr) {
    asm volatile("ldmatrix.sync.aligned.m8n8.x4.shared.b16 {%0,%1,%2,%3}, [%4];"
                 : "=r"(r[0]), "=r"(r[1]), "=r"(r[2]), "=r"(r[3]) : "r"(addr));
}
__device__ __forceinline__ void ldsm4t(uint32_t* r, uint32_t addr) {
    asm volatile("ldmatrix.sync.aligned.m8n8.x4.trans.shared.b16 {%0,%1,%2,%3}, [%4];"
                 : "=r"(r[0]), "=r"(r[1]), "=r"(r[2]), "=r"(r[3]) : "r"(addr));
}
__device__ __forceinline__ void cpa16(uint32_t dst, const void* src, uint32_t sz) {
    asm volatile("cp.async.cg.shared.global [%0], [%1], 16, %2;"
                 :: "r"(dst), "l"(src), "r"(sz) : "memory");
}
__device__ __forceinline__ void cpa_commit() { asm volatile("cp.async.commit_group;" ::: "memory"); }
__device__ __forceinline__ void cpa_wait1()  { asm volatile("cp.async.wait_group 1;" ::: "memory"); }
__device__ __forceinline__ void cpa_wait2()  { asm volatile("cp.async.wait_group 2;" ::: "memory"); }

// ---------------------------------------------------------------------------
// Single fused fp32->fp16 convert (x | w_qkv[0:1024r] | w_out), grid-stride.
// ---------------------------------------------------------------------------
__global__ __launch_bounds__(256)
void f2h_all(const float* __restrict__ x, const float* __restrict__ wqk,
             const float* __restrict__ wout,
             __half* __restrict__ dx, __half* __restrict__ dwqk,
             __half* __restrict__ dwout)
{
    const int NX = MTOT * 512;
    const int NW = 1024 * 512;
    const int NO = 512 * 512;
    const int total = (NX + NW + NO) / 8;
    for (int w = blockIdx.x * 256 + threadIdx.x; w < total; w += gridDim.x * 256) {
        int i = w * 8;
        const float* src; __half* dst; int off;
        if (i < NX)            { src = x;    dst = dx;    off = i; }
        else if (i < NX + NW)  { src = wqk;  dst = dwqk;  off = i - NX; }
        else                   { src = wout; dst = dwout; off = i - NX - NW; }
        float4 a = *(const float4*)(src + off);
        float4 b = *(const float4*)(src + off + 4);
        *(uint4*)(dst + off) = make_uint4(h2(a.x, a.y), h2(a.z, a.w),
                                          h2(b.x, b.y), h2(b.z, b.w));
    }
}

// ---------------------------------------------------------------------------
// GEMM: C[M,Nc] = A[M,K] @ B[Nc,K]^T (+bias), A,B fp16 K-major.
// CTA tile 128x64, BK=32, 4-stage cp.async (depth 2), ldmatrix fragments.
// 8 warps = 4(m) x 2(n); warp tile 32x32; acc 32 regs -> 3 CTAs/SM (24 warps).
// ---------------------------------------------------------------------------
#define GROWB 80                      // bytes per SMEM row (40 halves)
#define GSTG3 (192 * GROWB)           // per stage: A(128) + B(64) rows = 15360 B
#define GEMM_STAGES 4

template<bool OHALF>
__global__ __launch_bounds__(256, 3)
void gemm_h(const __half* __restrict__ A, const __half* __restrict__ Bm,
            const float* __restrict__ bias, void* __restrict__ Cp,
            int M, int Nc, int K)
{
    extern __shared__ char shb[];
    const uint32_t sb = smem_u32(shb);
    const int tid = threadIdx.x, lane = tid & 31, wid = tid >> 5;
    const int g = lane >> 2, tg = lane & 3;
    const int wm = (wid >> 1) * 32, wn = (wid & 1) * 32;

    const __half* Ab = A + (size_t)blockIdx.y * 128 * K;
    const __half* Bb = Bm + (size_t)blockIdx.x * 64 * K;
    const int arow = tid >> 1, ac = (tid & 1) * 32;      // A: 2 thr/row, 32B each
    const int brow = tid >> 2, bc = (tid & 3) * 16;      // B: 4 thr/row, 16B each
    const char* ag0 = (const char*)(Ab + (size_t)arow * K) + ac;
    const char* bg0 = (const char*)(Bb + (size_t)brow * K) + bc;

    uint32_t aoff[2], boff[2];
#pragma unroll
    for (int mt = 0; mt < 2; mt++)
        aoff[mt] = (wm + mt * 16 + (lane & 7) + ((lane >> 3) & 1) * 8) * GROWB + (lane >> 4) * 16;
#pragma unroll
    for (int ntp = 0; ntp < 2; ntp++)
        boff[ntp] = 128 * GROWB + (wn + ntp * 16 + (lane & 7) + (lane >> 4) * 8) * GROWB
                    + ((lane >> 3) & 1) * 16;

    const int T = K / 32;              // 16
    auto issue = [&](int t) {
        if (t < T) {
            uint32_t s = sb + (t % GEMM_STAGES) * GSTG3;
            uint32_t as = s + arow * GROWB + ac;
            uint32_t bs = s + 128 * GROWB + brow * GROWB + bc;
            const char* ag = ag0 + t * 64;
            const char* bg = bg0 + t * 64;
            cpa16(as, ag, 16);  cpa16(as + 16, ag + 16, 16);
            cpa16(bs, bg, 16);
        }
        cpa_commit();
    };

    float acc[2][4][4];
#pragma unroll
    for (int mt = 0; mt < 2; mt++)
#pragma unroll
        for (int nt = 0; nt < 4; nt++)
#pragma unroll
            for (int q = 0; q < 4; q++) acc[mt][nt][q] = 0.f;

    issue(0); issue(1); issue(2);
    for (int t = 0; t < T; t++) {
        cpa_wait2();
        __syncthreads();
        issue(t + 3);
        const uint32_t s = sb + (t % GEMM_STAGES) * GSTG3;
#pragma unroll
        for (int ks = 0; ks < 2; ks++) {
            uint32_t af[2][4];
            ldsm4(af[0], s + aoff[0] + ks * 32);
            ldsm4(af[1], s + aoff[1] + ks * 32);
#pragma unroll
            for (int ntp = 0; ntp < 2; ntp++) {
                uint32_t bf[4];
                ldsm4(bf, s + boff[ntp] + ks * 32);
#pragma unroll
                for (int mt = 0; mt < 2; mt++) {
                    mma16(acc[mt][ntp * 2],     af[mt][0], af[mt][1], af[mt][2], af[mt][3], bf[0], bf[1]);
                    mma16(acc[mt][ntp * 2 + 1], af[mt][0], af[mt][1], af[mt][2], af[mt][3], bf[2], bf[3]);
                }
            }
        }
    }

#pragma unroll
    for (int mt = 0; mt < 2; mt++) {
        int row = blockIdx.y * 128 + wm + mt * 16 + g;
#pragma unroll
        for (int nt = 0; nt < 4; nt++) {
            int col = blockIdx.x * 64 + wn + nt * 8 + tg * 2;
            float b0 = 0.f, b1 = 0.f;
            if (bias) { b0 = bias[col]; b1 = bias[col + 1]; }
            if (OHALF) {
                __half* C = (__half*)Cp;
                *(uint32_t*)(C + (size_t)row * Nc + col) =
                    h2(acc[mt][nt][0] + b0, acc[mt][nt][1] + b1);
                *(uint32_t*)(C + (size_t)(row + 8) * Nc + col) =
                    h2(acc[mt][nt][2] + b0, acc[mt][nt][3] + b1);
            } else {
                float* C = (float*)Cp;
                *(float2*)(C + (size_t)row * Nc + col) =
                    make_float2(acc[mt][nt][0] + b0, acc[mt][nt][1] + b1);
                *(float2*)(C + (size_t)(row + 8) * Nc + col) =
                    make_float2(acc[mt][nt][2] + b0, acc[mt][nt][3] + b1);
            }
        }
    }
}

// ---------------------------------------------------------------------------
// Windowed attention, 2 CTAs/SM (110,592 B smem). (R15 version — unchanged.)
// ---------------------------------------------------------------------------
#define A1STGB (320 * GROWB)          // 25600
#define SHP    264
#define VSTGB  (32 * SHP * 2)         // 16896
#define U_OFF  (64 * SHP * 2)         // 33792
#define ATTN_SMEM (U_OFF + 3 * A1STGB)// 110592

__global__ __launch_bounds__(256, 2)
void attn_h(const __half* __restrict__ qk, __half* __restrict__ outa)
{
    extern __shared__ char shb[];
    __half* Sh = (__half*)shb;                    // 64 x 264 fp16 (P)
    float* S = (float*)(shb + U_OFF);             // 64 x 260 fp32, aliases U
    const uint32_t sb = smem_u32(shb);
    const uint32_t sbSh = sb;
    const uint32_t sbU = sb + U_OFF;

    const int tid = threadIdx.x;
    const int lane = tid & 31, wid = tid >> 5;
    const int g = lane >> 2, tg = lane & 3;
    const int wm = (wid >> 2) * 32;
    const int wn = (wid & 3) * 64;

    const int z = blockIdx.x;
    const int b = z >> 7, r = z & 127, wb = r >> 1, half = r & 1;
    const __half* qbase = qk + ((size_t)(b * 8192 + wb * 128 + half * 64)) * 1024;
    const __half* kbase = qk + (size_t)b * 8192 * 1024 + 512;
    const int kn0 = wb * 128 - 128;
    const bool wactive = (half != 0) || (wn != 192);

    // ---- Phase 1: S = Q @ K2^T (3-stage cp.async + ldmatrix) ----------------
    {
        const int qrow = tid >> 2, qc = (tid & 3) * 16;
        const char* qg0 = (const char*)(qbase + (size_t)qrow * 1024) + qc;
        const char* kg0[4]; uint32_t ksz[4]; int krow[4];
#pragma unroll
        for (int u = 0; u < 4; u++) {
            krow[u] = qrow + 64 * u;
            int n = kn0 + krow[u];
            ksz[u] = (n >= 0 && (half || u < 3)) ? 16u : 0u;
            kg0[u] = (const char*)(kbase + (size_t)(n >= 0 ? n : 0) * 1024) + qc;
        }

        uint32_t aoff[2], boff[4];
#pragma unroll
        for (int mt = 0; mt < 2; mt++)
            aoff[mt] = (wm + mt * 16 + (lane & 7) + ((lane >> 3) & 1) * 8) * GROWB + (lane >> 4) * 16;
#pragma unroll
        for (int ntp = 0; ntp < 4; ntp++)
            boff[ntp] = 64 * GROWB + (wn + ntp * 16 + (lane & 7) + (lane >> 4) * 8) * GROWB
                        + ((lane >> 3) & 1) * 16;

        auto issue1 = [&](int t) {
            if (t < 16) {
                uint32_t s = sbU + (t % 3) * A1STGB;
                cpa16(s + qrow * GROWB + qc, qg0 + t * 64, 16);
#pragma unroll
                for (int u = 0; u < 4; u++)
                    cpa16(s + (64 + krow[u]) * GROWB + qc, kg0[u] + t * 64, ksz[u]);
            }
            cpa_commit();
        };

        float acc[2][8][4];
#pragma unroll
        for (int mt = 0; mt < 2; mt++)
#pragma unroll
            for (int nt = 0; nt < 8; nt++)
#pragma unroll
                for (int q = 0; q < 4; q++) acc[mt][nt][q] = 0.f;

        issue1(0); issue1(1);
        for (int t = 0; t < 16; t++) {
            cpa_wait1();
            __syncthreads();
            issue1(t + 2);
            const uint32_t s = sbU + (t % 3) * A1STGB;
            if (wactive) {
#pragma unroll
                for (int ks = 0; ks < 2; ks++) {
                    uint32_t af[2][4];
                    ldsm4(af[0], s + aoff[0] + ks * 32);
                    ldsm4(af[1], s + aoff[1] + ks * 32);
#pragma unroll
                    for (int ntp = 0; ntp < 4; ntp++) {
                        uint32_t bf[4];
                        ldsm4(bf, s + boff[ntp] + ks * 32);
#pragma unroll
                        for (int mt = 0; mt < 2; mt++) {
                            mma16(acc[mt][ntp * 2],     af[mt][0], af[mt][1], af[mt][2], af[mt][3], bf[0], bf[1]);
                            mma16(acc[mt][ntp * 2 + 1], af[mt][0], af[mt][1], af[mt][2], af[mt][3], bf[2], bf[3]);
                        }
                    }
                }
            }
        }
        __syncthreads();

        const float scale = 0.044194173824159216f;  // 512^-0.5
#pragma unroll
        for (int mt = 0; mt < 2; mt++) {
#pragma unroll
            for (int nt = 0; nt < 8; nt++) {
                int row0 = wm + mt * 16 + g;
                int col = wn + nt * 8 + tg * 2;
#pragma unroll
                for (int hh = 0; hh < 2; hh++) {
                    int row = row0 + hh * 8;
                    int lim = half * 64 + row + 128;
                    float v0 = acc[mt][nt][hh * 2 + 0] * scale;
                    float v1 = acc[mt][nt][hh * 2 + 1] * scale;
                    S[row * 260 + col]     = (col > lim)     ? -1e30f : v0;
                    S[row * 260 + col + 1] = (col + 1 > lim) ? -1e30f : v1;
                }
            }
        }
    }
    __syncthreads();

    // ---- Softmax (fp32 from S), write P fp16 into Sh -------------------------
    {
        int row = tid >> 2, l4 = tid & 3;
        const int cmax = half ? 256 : 192;
        float m = -1e30f;
        for (int c = l4; c < cmax; c += 4) m = fmaxf(m, S[row * 260 + c]);
        m = fmaxf(m, __shfl_xor_sync(0xffffffffu, m, 1));
        m = fmaxf(m, __shfl_xor_sync(0xffffffffu, m, 2));
        float s = 0.f;
        for (int c = l4; c < cmax; c += 4) {
            float e = __expf(S[row * 260 + c] - m);
            S[row * 260 + c] = e;
            s += e;
        }
        s += __shfl_xor_sync(0xffffffffu, s, 1);
        s += __shfl_xor_sync(0xffffffffu, s, 2);
        float inv = 1.f / s;
        for (int c = l4; c < cmax; c += 4)
            Sh[row * SHP + c] = __float2half_rn(S[row * 260 + c] * inv);
    }
    __syncthreads();

    // ---- Phase 2: O = P @ V (V := K rows, ref bug). jmax=6 when half==0 ------
    __half* outbase = outa + ((size_t)(b * 8192 + wb * 128 + half * 64)) * 512;
    const int vrow = tid >> 3, vcb = (tid & 7) * 64;
    const int jmax = half ? 8 : 6;

    uint32_t poff[2];
#pragma unroll
    for (int mt = 0; mt < 2; mt++)
        poff[mt] = sbSh + (wm + mt * 16 + (lane & 7) + ((lane >> 3) & 1) * 8) * (SHP * 2)
                   + (lane >> 4) * 16;

    for (int d0 = 0; d0 < 512; d0 += 256) {
        float acc2[2][8][4];
#pragma unroll
        for (int mt = 0; mt < 2; mt++)
#pragma unroll
            for (int nt = 0; nt < 8; nt++)
#pragma unroll
                for (int q = 0; q < 4; q++) acc2[mt][nt][q] = 0.f;

        auto issue2 = [&](int t) {
            if (t < jmax) {
                int n = kn0 + t * 32 + vrow;
                uint32_t sz = (n >= 0) ? 16u : 0u;
                const char* src = (const char*)(kbase + (size_t)(n >= 0 ? n : 0) * 1024 + d0) + vcb;
                uint32_t vd = sbU + (t & 3) * VSTGB + vrow * (SHP * 2) + vcb;
#pragma unroll
                for (int u = 0; u < 4; u++)
                    cpa16(vd + u * 16, src + u * 16, sz);
            }
            cpa_commit();
        };

        issue2(0); issue2(1); issue2(2);
        for (int t = 0; t < jmax; t++) {
            cpa_wait2();
            __syncthreads();
            issue2(t + 3);
            const uint32_t vs = sbU + (t & 3) * VSTGB;
            const int j0 = t * 32;
#pragma unroll
            for (int ks = 0; ks < 2; ks++) {
                uint32_t af[2][4];
                ldsm4(af[0], poff[0] + (j0 + ks * 16) * 2);
                ldsm4(af[1], poff[1] + (j0 + ks * 16) * 2);
#pragma unroll
                for (int ntp = 0; ntp < 4; ntp++) {
                    uint32_t bf[4];
                    ldsm4t(bf, vs + (ks * 16 + (lane & 7) + ((lane >> 3) & 1) * 8) * (SHP * 2)
                               + (wn + ntp * 16 + (lane >> 4) * 8) * 2);
#pragma unroll
                    for (int mt = 0; mt < 2; mt++) {
                        mma16(acc2[mt][ntp * 2],     af[mt][0], af[mt][1], af[mt][2], af[mt][3], bf[0], bf[1]);
                        mma16(acc2[mt][ntp * 2 + 1], af[mt][0], af[mt][1], af[mt][2], af[mt][3], bf[2], bf[3]);
                    }
                }
            }
        }

#pragma unroll
        for (int mt = 0; mt < 2; mt++) {
            int row = wm + mt * 16 + g;
#pragma unroll
            for (int nt = 0; nt < 8; nt++) {
                int col = d0 + wn + nt * 8 + tg * 2;
                *(uint32_t*)(outbase + (size_t)row * 512 + col) =
                    h2(acc2[mt][nt][0], acc2[mt][nt][1]);
                *(uint32_t*)(outbase + (size_t)(row + 8) * 512 + col) =
                    h2(acc2[mt][nt][2], acc2[mt][nt][3]);
            }
        }
        __syncthreads();
    }
}

// ---------------------------------------------------------------------------
extern "C" void kernel_launch(void* const* d_in, const int* in_sizes, int n_in,
                              void* d_out, int out_size)
{
    const float* x     = (const float*)d_in[0];   // (4, 8192, 512)
    const float* w_qkv = (const float*)d_in[1];   // (1536, 512) — V rows dead (ref bug)
    const float* w_out = (const float*)d_in[2];   // (512, 512)
    const float* b_out = (const float*)d_in[3];   // (512,)
    float* out = (float*)d_out;

    __half *xbuf, *wqkbuf, *woutbuf, *qkbuf, *attbuf;
    cudaGetSymbolAddress((void**)&xbuf,   g_x);
    cudaGetSymbolAddress((void**)&wqkbuf, g_wqk);
    cudaGetSymbolAddress((void**)&woutbuf,g_wout);
    cudaGetSymbolAddress((void**)&qkbuf,  g_qk);
    cudaGetSymbolAddress((void**)&attbuf, g_att);

    const int gemm_smem = GEMM_STAGES * GSTG3;    // 61440 B (3 CTAs/SM)
    cudaFuncSetAttribute(gemm_h<true>,  cudaFuncAttributeMaxDynamicSharedMemorySize, gemm_smem);
    cudaFuncSetAttribute(gemm_h<false>, cudaFuncAttributeMaxDynamicSharedMemorySize, gemm_smem);
    cudaFuncSetAttribute(attn_h, cudaFuncAttributeMaxDynamicSharedMemorySize, ATTN_SMEM);

    // 0) fp32 -> fp16 conversions (single fused launch, grid-stride)
    f2h_all<<<1184, 256>>>(x, w_qkv, w_out, xbuf, wqkbuf, woutbuf);

    // 1) Q,K projection: [32768,512] @ [1024,512]^T -> g_qk (fp16)
    dim3 g1(1024 / 64, MTOT / 128);
    gemm_h<true><<<g1, 256, gemm_smem>>>(xbuf, wqkbuf, nullptr, qkbuf, MTOT, 1024, 512);

    // 2) Windowed attention (V := K per reference bug) -> g_att (fp16)
    attn_h<<<512, 256, ATTN_SMEM>>>(qkbuf, attbuf);

    // 3) Output projection + bias: [32768,512](fp16) @ [512,512]^T -> out (fp32)
    dim3 g3(512 / 64, MTOT / 128);
    gemm_h<false><<<g3, 256, gemm_smem>>>(attbuf, woutbuf, b_out, out, MTOT, 512, 512);
}

// round 17
// speedup vs baseline: 1.1101x; 1.1101x over previous
#include <cuda_runtime.h>
#include <cuda_fp16.h>
#include <cstdint>
#include <cstddef>

// B=4, N=8192, DIN=512, DINNER=512, DOUT=512, W=128 -> 64 windows/batch, pad=0
#define MTOT 32768

// Scratch (alloc-guard-safe __device__ globals), all fp16
__device__ __half g_x[(size_t)MTOT * 512];
__device__ __half g_wqk[(size_t)1024 * 512];
__device__ __half g_wout[(size_t)512 * 512];
__device__ __half g_qk[(size_t)MTOT * 1024];   // [m][0:512]=Q, [m][512:1024]=K
__device__ __half g_att[(size_t)MTOT * 512];

__device__ __forceinline__ uint32_t h2(float a, float b) {
    __half2 h = __floats2half2_rn(a, b);
    return *(uint32_t*)&h;
}
__device__ __forceinline__ uint32_t smem_u32(const void* p) {
    uint32_t a;
    asm("{ .reg .u64 t; cvta.to.shared.u64 t, %1; cvt.u32.u64 %0, t; }" : "=r"(a) : "l"(p));
    return a;
}
__device__ __forceinline__ void mma16(float* c, uint32_t a0, uint32_t a1, uint32_t a2, uint32_t a3,
                                      uint32_t b0, uint32_t b1) {
    asm volatile("mma.sync.aligned.m16n8k16.row.col.f32.f16.f16.f32 "
                 "{%0,%1,%2,%3}, {%4,%5,%6,%7}, {%8,%9}, {%0,%1,%2,%3};"
                 : "+f"(c[0]), "+f"(c[1]), "+f"(c[2]), "+f"(c[3])
                 : "r"(a0), "r"(a1), "r"(a2), "r"(a3), "r"(b0), "r"(b1));
}
__device__ __forceinline__ void ldsm4(uint32_t* r, uint32_t addr) {
    asm volatile("ldmatrix.sync.aligned.m8n8.x4.shared.b16 {%0,%1,%2,%3}, [%4];"
                 : "=r"(r[0]), "=r"(r[1]), "=r"(r[2]), "=r"(r[3]) : "r"(addr));
}
__device__ __forceinline__ void ldsm4t(uint32_t* r, uint32_t addr) {
    asm volatile("ldmatrix.sync.aligned.m8n8.x4.trans.shared.b16 {%0,%1,%2,%3}, [%4];"
                 : "=r"(r[0]), "=r"(r[1]), "=r"(r[2]), "=r"(r[3]) : "r"(addr));
}
__device__ __forceinline__ void cpa16(uint32_t dst, const void* src, uint32_t sz) {
    asm volatile("cp.async.cg.shared.global [%0], [%1], 16, %2;"
                 :: "r"(dst), "l"(src), "r"(sz) : "memory");
}
__device__ __forceinline__ void cpa_commit() { asm volatile("cp.async.commit_group;" ::: "memory"); }
__device__ __forceinline__ void cpa_wait1()  { asm volatile("cp.async.wait_group 1;" ::: "memory"); }
__device__ __forceinline__ void cpa_wait2()  { asm volatile("cp.async.wait_group 2;" ::: "memory"); }

// ---------------------------------------------------------------------------
// Single fused fp32->fp16 convert (x | w_qkv[0:1024r] | w_out), grid-stride.
// ---------------------------------------------------------------------------
__global__ __launch_bounds__(256)
void f2h_all(const float* __restrict__ x, const float* __restrict__ wqk,
             const float* __restrict__ wout,
             __half* __restrict__ dx, __half* __restrict__ dwqk,
             __half* __restrict__ dwout)
{
    const int NX = MTOT * 512;
    const int NW = 1024 * 512;
    const int NO = 512 * 512;
    const int total = (NX + NW + NO) / 8;
    for (int w = blockIdx.x * 256 + threadIdx.x; w < total; w += gridDim.x * 256) {
        int i = w * 8;
        const float* src; __half* dst; int off;
        if (i < NX)            { src = x;    dst = dx;    off = i; }
        else if (i < NX + NW)  { src = wqk;  dst = dwqk;  off = i - NX; }
        else                   { src = wout; dst = dwout; off = i - NX - NW; }
        float4 a = *(const float4*)(src + off);
        float4 b = *(const float4*)(src + off + 4);
        *(uint4*)(dst + off) = make_uint4(h2(a.x, a.y), h2(a.z, a.w),
                                          h2(b.x, b.y), h2(b.z, b.w));
    }
}

// ---------------------------------------------------------------------------
// GEMM: C[M,Nc] = A[M,K] @ B[Nc,K]^T (+bias), A,B fp16 K-major.
// 128x128x32 tiles, 4-stage cp.async (depth 2), ldmatrix fragments.
// 8 warps = 4(m) x 2(n); warp tile 32x64. 2 CTAs/SM. (R15 config.)
// OHALF: epilogue stages C tile in SMEM (pitch 136 halves -> STS bank g*4+tg,
// conflict-free) then writes fully coalesced 16B rows.
// ---------------------------------------------------------------------------
#define GROWB 80                      // bytes per SMEM row (40 halves)
#define GSTGB (256 * GROWB)           // per stage: A(128) + B(128) rows = 20480 B
#define GEMM_STAGES 4
#define CSP 136                       // epilogue C-tile pitch in halves

template<bool OHALF>
__global__ __launch_bounds__(256, 2)
void gemm_h(const __half* __restrict__ A, const __half* __restrict__ Bm,
            const float* __restrict__ bias, void* __restrict__ Cp,
            int M, int Nc, int K)
{
    extern __shared__ char shb[];
    const uint32_t sb = smem_u32(shb);
    const int tid = threadIdx.x, lane = tid & 31, wid = tid >> 5;
    const int g = lane >> 2, tg = lane & 3;
    const int wm = (wid >> 1) * 32, wn = (wid & 1) * 64;

    const __half* Ab = A + (size_t)blockIdx.y * 128 * K;
    const __half* Bb = Bm + (size_t)blockIdx.x * 128 * K;
    const int crow = tid >> 1, cc = (tid & 1) * 32;      // row + 32B half-row
    const char* ag0 = (const char*)(Ab + (size_t)crow * K) + cc;
    const char* bg0 = (const char*)(Bb + (size_t)crow * K) + cc;

    uint32_t aoff[2], boff[4];
#pragma unroll
    for (int mt = 0; mt < 2; mt++)
        aoff[mt] = (wm + mt * 16 + (lane & 7) + ((lane >> 3) & 1) * 8) * GROWB + (lane >> 4) * 16;
#pragma unroll
    for (int ntp = 0; ntp < 4; ntp++)
        boff[ntp] = 128 * GROWB + (wn + ntp * 16 + (lane & 7) + (lane >> 4) * 8) * GROWB
                    + ((lane >> 3) & 1) * 16;

    const int T = K / 32;              // 16
    auto issue = [&](int t) {
        if (t < T) {
            uint32_t s = sb + (t % GEMM_STAGES) * GSTGB;
            uint32_t as = s + crow * GROWB + cc;
            uint32_t bs = s + 128 * GROWB + crow * GROWB + cc;
            const char* ag = ag0 + t * 64;
            const char* bg = bg0 + t * 64;
            cpa16(as, ag, 16);       cpa16(as + 16, ag + 16, 16);
            cpa16(bs, bg, 16);       cpa16(bs + 16, bg + 16, 16);
        }
        cpa_commit();
    };

    float acc[2][8][4];
#pragma unroll
    for (int mt = 0; mt < 2; mt++)
#pragma unroll
        for (int nt = 0; nt < 8; nt++)
#pragma unroll
            for (int q = 0; q < 4; q++) acc[mt][nt][q] = 0.f;

    issue(0); issue(1); issue(2);
    for (int t = 0; t < T; t++) {
        cpa_wait2();
        __syncthreads();
        issue(t + 3);
        const uint32_t s = sb + (t % GEMM_STAGES) * GSTGB;
#pragma unroll
        for (int ks = 0; ks < 2; ks++) {
            uint32_t af[2][4];
            ldsm4(af[0], s + aoff[0] + ks * 32);
            ldsm4(af[1], s + aoff[1] + ks * 32);
#pragma unroll
            for (int ntp = 0; ntp < 4; ntp++) {
                uint32_t bf[4];
                ldsm4(bf, s + boff[ntp] + ks * 32);
#pragma unroll
                for (int mt = 0; mt < 2; mt++) {
                    mma16(acc[mt][ntp * 2],     af[mt][0], af[mt][1], af[mt][2], af[mt][3], bf[0], bf[1]);
                    mma16(acc[mt][ntp * 2 + 1], af[mt][0], af[mt][1], af[mt][2], af[mt][3], bf[2], bf[3]);
                }
            }
        }
    }

    if (OHALF) {
        // ---- staged fp16 epilogue: SMEM transpose-free coalescing ----------
        __syncthreads();                       // all warps done with stage smem
        __half* Cs = (__half*)shb;             // 128 x CSP halves = 34,816 B
#pragma unroll
        for (int mt = 0; mt < 2; mt++) {
            int lrow = wm + mt * 16 + g;
#pragma unroll
            for (int nt = 0; nt < 8; nt++) {
                int lcol = wn + nt * 8 + tg * 2;
                float b0 = 0.f, b1 = 0.f;
                if (bias) {
                    b0 = bias[blockIdx.x * 128 + lcol];
                    b1 = bias[blockIdx.x * 128 + lcol + 1];
                }
                *(uint32_t*)(Cs + lrow * CSP + lcol) =
                    h2(acc[mt][nt][0] + b0, acc[mt][nt][1] + b1);
                *(uint32_t*)(Cs + (lrow + 8) * CSP + lcol) =
                    h2(acc[mt][nt][2] + b0, acc[mt][nt][3] + b1);
            }
        }
        __syncthreads();
        __half* C = (__half*)Cp;
        // 128 rows x 16 chunks of 16B; 8 chunks per thread, fully coalesced
#pragma unroll
        for (int it = 0; it < 8; it++) {
            int idx = tid + it * 256;
            int row = idx >> 4, ch = idx & 15;
            uint4 v = *(uint4*)(Cs + row * CSP + ch * 8);
            *(uint4*)(C + (size_t)(blockIdx.y * 128 + row) * Nc
                        + blockIdx.x * 128 + ch * 8) = v;
        }
    } else {
#pragma unroll
        for (int mt = 0; mt < 2; mt++) {
            int row = blockIdx.y * 128 + wm + mt * 16 + g;
#pragma unroll
            for (int nt = 0; nt < 8; nt++) {
                int col = blockIdx.x * 128 + wn + nt * 8 + tg * 2;
                float b0 = 0.f, b1 = 0.f;
                if (bias) { b0 = bias[col]; b1 = bias[col + 1]; }
                float* C = (float*)Cp;
                *(float2*)(C + (size_t)row * Nc + col) =
                    make_float2(acc[mt][nt][0] + b0, acc[mt][nt][1] + b1);
                *(float2*)(C + (size_t)(row + 8) * Nc + col) =
                    make_float2(acc[mt][nt][2] + b0, acc[mt][nt][3] + b1);
            }
        }
    }
}

// ---------------------------------------------------------------------------
// Windowed attention, 2 CTAs/SM (110,592 B smem). (R15 version — unchanged.)
// ---------------------------------------------------------------------------
#define A1STGB (320 * GROWB)          // 25600
#define SHP    264
#define VSTGB  (32 * SHP * 2)         // 16896
#define U_OFF  (64 * SHP * 2)         // 33792
#define ATTN_SMEM (U_OFF + 3 * A1STGB)// 110592

__global__ __launch_bounds__(256, 2)
void attn_h(const __half* __restrict__ qk, __half* __restrict__ outa)
{
    extern __shared__ char shb[];
    __half* Sh = (__half*)shb;                    // 64 x 264 fp16 (P)
    float* S = (float*)(shb + U_OFF);             // 64 x 260 fp32, aliases U
    const uint32_t sb = smem_u32(shb);
    const uint32_t sbSh = sb;
    const uint32_t sbU = sb + U_OFF;

    const int tid = threadIdx.x;
    const int lane = tid & 31, wid = tid >> 5;
    const int g = lane >> 2, tg = lane & 3;
    const int wm = (wid >> 2) * 32;
    const int wn = (wid & 3) * 64;

    const int z = blockIdx.x;
    const int b = z >> 7, r = z & 127, wb = r >> 1, half = r & 1;
    const __half* qbase = qk + ((size_t)(b * 8192 + wb * 128 + half * 64)) * 1024;
    const __half* kbase = qk + (size_t)b * 8192 * 1024 + 512;
    const int kn0 = wb * 128 - 128;
    const bool wactive = (half != 0) || (wn != 192);

    // ---- Phase 1: S = Q @ K2^T (3-stage cp.async + ldmatrix) ----------------
    {
        const int qrow = tid >> 2, qc = (tid & 3) * 16;
        const char* qg0 = (const char*)(qbase + (size_t)qrow * 1024) + qc;
        const char* kg0[4]; uint32_t ksz[4]; int krow[4];
#pragma unroll
        for (int u = 0; u < 4; u++) {
            krow[u] = qrow + 64 * u;
            int n = kn0 + krow[u];
            ksz[u] = (n >= 0 && (half || u < 3)) ? 16u : 0u;
            kg0[u] = (const char*)(kbase + (size_t)(n >= 0 ? n : 0) * 1024) + qc;
        }

        uint32_t aoff[2], boff[4];
#pragma unroll
        for (int mt = 0; mt < 2; mt++)
            aoff[mt] = (wm + mt * 16 + (lane & 7) + ((lane >> 3) & 1) * 8) * GROWB + (lane >> 4) * 16;
#pragma unroll
        for (int ntp = 0; ntp < 4; ntp++)
            boff[ntp] = 64 * GROWB + (wn + ntp * 16 + (lane & 7) + (lane >> 4) * 8) * GROWB
                        + ((lane >> 3) & 1) * 16;

        auto issue1 = [&](int t) {
            if (t < 16) {
                uint32_t s = sbU + (t % 3) * A1STGB;
                cpa16(s + qrow * GROWB + qc, qg0 + t * 64, 16);
#pragma unroll
                for (int u = 0; u < 4; u++)
                    cpa16(s + (64 + krow[u]) * GROWB + qc, kg0[u] + t * 64, ksz[u]);
            }
            cpa_commit();
        };

        float acc[2][8][4];
#pragma unroll
        for (int mt = 0; mt < 2; mt++)
#pragma unroll
            for (int nt = 0; nt < 8; nt++)
#pragma unroll
                for (int q = 0; q < 4; q++) acc[mt][nt][q] = 0.f;

        issue1(0); issue1(1);
        for (int t = 0; t < 16; t++) {
            cpa_wait1();
            __syncthreads();
            issue1(t + 2);
            const uint32_t s = sbU + (t % 3) * A1STGB;
            if (wactive) {
#pragma unroll
                for (int ks = 0; ks < 2; ks++) {
                    uint32_t af[2][4];
                    ldsm4(af[0], s + aoff[0] + ks * 32);
                    ldsm4(af[1], s + aoff[1] + ks * 32);
#pragma unroll
                    for (int ntp = 0; ntp < 4; ntp++) {
                        uint32_t bf[4];
                        ldsm4(bf, s + boff[ntp] + ks * 32);
#pragma unroll
                        for (int mt = 0; mt < 2; mt++) {
                            mma16(acc[mt][ntp * 2],     af[mt][0], af[mt][1], af[mt][2], af[mt][3], bf[0], bf[1]);
                            mma16(acc[mt][ntp * 2 + 1], af[mt][0], af[mt][1], af[mt][2], af[mt][3], bf[2], bf[3]);
                        }
                    }
                }
            }
        }
        __syncthreads();

        const float scale = 0.044194173824159216f;  // 512^-0.5
#pragma unroll
        for (int mt = 0; mt < 2; mt++) {
#pragma unroll
            for (int nt = 0; nt < 8; nt++) {
                int row0 = wm + mt * 16 + g;
                int col = wn + nt * 8 + tg * 2;
#pragma unroll
                for (int hh = 0; hh < 2; hh++) {
                    int row = row0 + hh * 8;
                    int lim = half * 64 + row + 128;
                    float v0 = acc[mt][nt][hh * 2 + 0] * scale;
                    float v1 = acc[mt][nt][hh * 2 + 1] * scale;
                    S[row * 260 + col]     = (col > lim)     ? -1e30f : v0;
                    S[row * 260 + col + 1] = (col + 1 > lim) ? -1e30f : v1;
                }
            }
        }
    }
    __syncthreads();

    // ---- Softmax (fp32 from S), write P fp16 into Sh -------------------------
    {
        int row = tid >> 2, l4 = tid & 3;
        const int cmax = half ? 256 : 192;
        float m = -1e30f;
        for (int c = l4; c < cmax; c += 4) m = fmaxf(m, S[row * 260 + c]);
        m = fmaxf(m, __shfl_xor_sync(0xffffffffu, m, 1));
        m = fmaxf(m, __shfl_xor_sync(0xffffffffu, m, 2));
        float s = 0.f;
        for (int c = l4; c < cmax; c += 4) {
            float e = __expf(S[row * 260 + c] - m);
            S[row * 260 + c] = e;
            s += e;
        }
        s += __shfl_xor_sync(0xffffffffu, s, 1);
        s += __shfl_xor_sync(0xffffffffu, s, 2);
        float inv = 1.f / s;
        for (int c = l4; c < cmax; c += 4)
            Sh[row * SHP + c] = __float2half_rn(S[row * 260 + c] * inv);
    }
    __syncthreads();

    // ---- Phase 2: O = P @ V (V := K rows, ref bug). jmax=6 when half==0 ------
    __half* outbase = outa + ((size_t)(b * 8192 + wb * 128 + half * 64)) * 512;
    const int vrow = tid >> 3, vcb = (tid & 7) * 64;
    const int jmax = half ? 8 : 6;

    uint32_t poff[2];
#pragma unroll
    for (int mt = 0; mt < 2; mt++)
        poff[mt] = sbSh + (wm + mt * 16 + (lane & 7) + ((lane >> 3) & 1) * 8) * (SHP * 2)
                   + (lane >> 4) * 16;

    for (int d0 = 0; d0 < 512; d0 += 256) {
        float acc2[2][8][4];
#pragma unroll
        for (int mt = 0; mt < 2; mt++)
#pragma unroll
            for (int nt = 0; nt < 8; nt++)
#pragma unroll
                for (int q = 0; q < 4; q++) acc2[mt][nt][q] = 0.f;

        auto issue2 = [&](int t) {
            if (t < jmax) {
                int n = kn0 + t * 32 + vrow;
                uint32_t sz = (n >= 0) ? 16u : 0u;
                const char* src = (const char*)(kbase + (size_t)(n >= 0 ? n : 0) * 1024 + d0) + vcb;
                uint32_t vd = sbU + (t & 3) * VSTGB + vrow * (SHP * 2) + vcb;
#pragma unroll
                for (int u = 0; u < 4; u++)
                    cpa16(vd + u * 16, src + u * 16, sz);
            }
            cpa_commit();
        };

        issue2(0); issue2(1); issue2(2);
        for (int t = 0; t < jmax; t++) {
            cpa_wait2();
            __syncthreads();
            issue2(t + 3);
            const uint32_t vs = sbU + (t & 3) * VSTGB;
            const int j0 = t * 32;
#pragma unroll
            for (int ks = 0; ks < 2; ks++) {
                uint32_t af[2][4];
                ldsm4(af[0], poff[0] + (j0 + ks * 16) * 2);
                ldsm4(af[1], poff[1] + (j0 + ks * 16) * 2);
#pragma unroll
                for (int ntp = 0; ntp < 4; ntp++) {
                    uint32_t bf[4];
                    ldsm4t(bf, vs + (ks * 16 + (lane & 7) + ((lane >> 3) & 1) * 8) * (SHP * 2)
                               + (wn + ntp * 16 + (lane >> 4) * 8) * 2);
#pragma unroll
                    for (int mt = 0; mt < 2; mt++) {
                        mma16(acc2[mt][ntp * 2],     af[mt][0], af[mt][1], af[mt][2], af[mt][3], bf[0], bf[1]);
                        mma16(acc2[mt][ntp * 2 + 1], af[mt][0], af[mt][1], af[mt][2], af[mt][3], bf[2], bf[3]);
                    }
                }
            }
        }

#pragma unroll
        for (int mt = 0; mt < 2; mt++) {
            int row = wm + mt * 16 + g;
#pragma unroll
            for (int nt = 0; nt < 8; nt++) {
                int col = d0 + wn + nt * 8 + tg * 2;
                *(uint32_t*)(outbase + (size_t)row * 512 + col) =
                    h2(acc2[mt][nt][0], acc2[mt][nt][1]);
                *(uint32_t*)(outbase + (size_t)(row + 8) * 512 + col) =
                    h2(acc2[mt][nt][2], acc2[mt][nt][3]);
            }
        }
        __syncthreads();
    }
}

// ---------------------------------------------------------------------------
extern "C" void kernel_launch(void* const* d_in, const int* in_sizes, int n_in,
                              void* d_out, int out_size)
{
    const float* x     = (const float*)d_in[0];   // (4, 8192, 512)
    const float* w_qkv = (const float*)d_in[1];   // (1536, 512) — V rows dead (ref bug)
    const float* w_out = (const float*)d_in[2];   // (512, 512)
    const float* b_out = (const float*)d_in[3];   // (512,)
    float* out = (float*)d_out;

    __half *xbuf, *wqkbuf, *woutbuf, *qkbuf, *attbuf;
    cudaGetSymbolAddress((void**)&xbuf,   g_x);
    cudaGetSymbolAddress((void**)&wqkbuf, g_wqk);
    cudaGetSymbolAddress((void**)&woutbuf,g_wout);
    cudaGetSymbolAddress((void**)&qkbuf,  g_qk);
    cudaGetSymbolAddress((void**)&attbuf, g_att);

    const int gemm_smem = GEMM_STAGES * GSTGB;    // 81920 B (2 CTAs/SM)
    cudaFuncSetAttribute(gemm_h<true>,  cudaFuncAttributeMaxDynamicSharedMemorySize, gemm_smem);
    cudaFuncSetAttribute(gemm_h<false>, cudaFuncAttributeMaxDynamicSharedMemorySize, gemm_smem);
    cudaFuncSetAttribute(attn_h, cudaFuncAttributeMaxDynamicSharedMemorySize, ATTN_SMEM);

    // 0) fp32 -> fp16 conversions (single fused launch, grid-stride)
    f2h_all<<<1184, 256>>>(x, w_qkv, w_out, xbuf, wqkbuf, woutbuf);

    // 1) Q,K projection: [32768,512] @ [1024,512]^T -> g_qk (fp16)
    dim3 g1(1024 / 128, MTOT / 128);
    gemm_h<true><<<g1, 256, gemm_smem>>>(xbuf, wqkbuf, nullptr, qkbuf, MTOT, 1024, 512);

    // 2) Windowed attention (V := K per reference bug) -> g_att (fp16)
    attn_h<<<512, 256, ATTN_SMEM>>>(qkbuf, attbuf);

    // 3) Output projection + bias: [32768,512](fp16) @ [512,512]^T -> out (fp32)
    dim3 g3(512 / 128, MTOT / 128);
    gemm_h<false><<<g3, 256, gemm_smem>>>(attbuf, woutbuf, b_out, out, MTOT, 512, 512);
}